// round 11
// baseline (speedup 1.0000x reference)
#include <cuda_runtime.h>
#include <cuda_fp16.h>
#include <math.h>
#include <stdint.h>

// ---------------- problem constants ----------------
#define NB    4
#define NC    32
#define NSP   1024
#define ND    1024
#define NBH   16
#define SCALE 0.17677669529663687f   // 1/sqrt(32)
#define EPSGN 1e-5f

// ---------------- scratch (device globals; allocation-free) ----------------
__device__ float g_Q  [NBH * ND * NSP];       // q natural [bh][d][n] fp32 (pre-softmax)
__device__ float g_K  [NBH * ND * NSP];       // k natural [bh][d][n] fp32 (pre-softmax)
__device__ float g_X  [NBH * ND * NSP];       // attention out [bh][e][n] fp32
__device__ float g_Y  [NB * NC * NSP];        // projection out, pre-GN
__device__ float g_stats[8];                  // mean[4], var[4]
__device__ float g_qinv[NBH * NSP];           // 256 / sum(exp(q)) per (z,n)

// f16 operand arrays, TILE-PACKED + PRE-SWIZZLED:
// layout: [z][tile(8)][kchunk(32)] blocks of 8192B; block = 128 rows x 64B,
// element (r, kk): byte r*64 + (((kk>>3)+(r>>1))&3)*16 + (kk&7)*2
#define HFN (NBH * ND * NSP / 8)
__device__ uint4 g_Vf4[HFN];   // v  [e][n]             f16
__device__ uint4 g_Kf4[HFN];   // 256*k-softmax [d][n]  f16
__device__ uint4 g_Qf4[HFN];   // 256*q-softmax^T [n][d] f16
__device__ uint4 g_Cf4[HFN];   // ctx^T [e][d]          f16

// ---------------- small helpers ----------------
__device__ __forceinline__ uint32_t smem_u32(const void* p) {
    uint32_t a;
    asm("{ .reg .u64 t; cvta.to.shared.u64 t, %1; cvt.u32.u64 %0, t; }" : "=r"(a) : "l"(p));
    return a;
}
__device__ __forceinline__ unsigned packh2(float a, float b) {
    __half2 p = __floats2half2_rn(a, b);
    return *reinterpret_cast<unsigned*>(&p);
}
// byte offset of element (row, k) of matrix z in packed-swizzled layout
__device__ __forceinline__ size_t pkoff(int z, int row, int k) {
    size_t blk = (size_t)(z * 8 + (row >> 7)) * 32 + (k >> 5);
    int r = row & 127, kk = k & 31;
    return blk * 8192 +
           (uint32_t)(r * 64 + ((((kk >> 3) + (r >> 1)) & 3) << 4) + (kk & 7) * 2);
}
// in-smem 16B-chunk address within an 8KB region (same swizzle)
__device__ __forceinline__ uint32_t swzoff(int R, int ch) {
    return (uint32_t)(R * 64 + (((ch + (R >> 1)) & 3) << 4));
}
__device__ __forceinline__ void mbar_init(uint32_t a, uint32_t cnt) {
    asm volatile("mbarrier.init.shared.b64 [%0], %1;" :: "r"(a), "r"(cnt) : "memory");
}
__device__ __forceinline__ void mbar_expect_tx(uint32_t a, uint32_t tx) {
    asm volatile("mbarrier.arrive.expect_tx.shared.b64 _, [%0], %1;"
                 :: "r"(a), "r"(tx) : "memory");
}
__device__ __forceinline__ void mbar_wait(uint32_t a, uint32_t phase) {
    asm volatile(
        "{\n\t.reg .pred P;\n"
        "W%=:\n\t"
        "mbarrier.try_wait.parity.shared::cta.b64 P, [%0], %1;\n\t"
        "@!P bra W%=;\n\t}"
        :: "r"(a), "r"(phase) : "memory");
}
__device__ __forceinline__ void bulkcp(uint32_t sdst, const void* gsrc,
                                       uint32_t bytes, uint32_t mb) {
    asm volatile(
        "cp.async.bulk.shared::cta.global.mbarrier::complete_tx::bytes [%0], [%1], %2, [%3];"
        :: "r"(sdst), "l"(gsrc), "r"(bytes), "r"(mb) : "memory");
}
__device__ __forceinline__ void ldsm4(unsigned* r, uint32_t addr) {
    asm volatile("ldmatrix.sync.aligned.m8n8.x4.shared.b16 {%0,%1,%2,%3}, [%4];"
                 : "=r"(r[0]), "=r"(r[1]), "=r"(r[2]), "=r"(r[3]) : "r"(addr));
}
__device__ __forceinline__ void mma16816(float* c, const unsigned* a, const unsigned* b) {
    asm volatile(
        "mma.sync.aligned.m16n8k16.row.col.f32.f16.f16.f32 "
        "{%0,%1,%2,%3}, {%4,%5,%6,%7}, {%8,%9}, {%0,%1,%2,%3};"
        : "+f"(c[0]), "+f"(c[1]), "+f"(c[2]), "+f"(c[3])
        : "r"(a[0]), "r"(a[1]), "r"(a[2]), "r"(a[3]), "r"(b[0]), "r"(b[1]));
}

// ============================================================
// Kernel 1: QKV projection. q,k -> fp32 natural; v -> f16 packed.
// ============================================================
__global__ __launch_bounds__(256) void qkv_kernel(const float* __restrict__ img,
                                                  const float* __restrict__ w,
                                                  const float* __restrict__ bias) {
    __shared__ float xs[32][128];
    __shared__ float ws[64][32];
    __shared__ float bs[64];

    const int b  = blockIdx.z;
    const int o0 = blockIdx.y * 64;
    const int n0 = blockIdx.x * 128;
    const int t  = threadIdx.x;

#pragma unroll
    for (int i = 0; i < 4; i++) {
        int idx = t + 256 * i;
        int c = idx >> 5, c4 = (idx & 31) << 2;
        *(float4*)&xs[c][c4] = *(const float4*)&img[((size_t)b * 32 + c) * 1024 + n0 + c4];
    }
#pragma unroll
    for (int i = 0; i < 2; i++) {
        int idx = t + 256 * i;
        int o = idx >> 3, c4 = (idx & 7) << 2;
        *(float4*)&ws[o][c4] = *(const float4*)&w[(size_t)(o0 + o) * 32 + c4];
    }
    if (t < 64) bs[t] = bias[o0 + t];
    __syncthreads();

    const int tx = t & 31;
    const int oy = t >> 5;

    float acc[8][4];
#pragma unroll
    for (int r = 0; r < 8; r++) {
        float bv = bs[8 * oy + r];
#pragma unroll
        for (int i = 0; i < 4; i++) acc[r][i] = bv;
    }
#pragma unroll
    for (int c = 0; c < 32; c++) {
        float4 x = *(const float4*)&xs[c][4 * tx];
#pragma unroll
        for (int r = 0; r < 8; r++) {
            float wv = ws[8 * oy + r][c];
            acc[r][0] += wv * x.x; acc[r][1] += wv * x.y;
            acc[r][2] += wv * x.z; acc[r][3] += wv * x.w;
        }
    }

    const int nglob = n0 + 4 * tx;
#pragma unroll
    for (int r = 0; r < 8; r++) {
        int o     = o0 + 8 * oy + r;
        int which = o >> 12;
        int oc    = o & 4095;
        int h     = oc & 3;
        int cch   = oc >> 2;
        int zz    = b * 4 + h;
        if (which == 2) {
            uint2 hv;
            hv.x = packh2(acc[r][0], acc[r][1]);
            hv.y = packh2(acc[r][2], acc[r][3]);
            *(uint2*)((char*)g_Vf4 + pkoff(zz, cch, nglob)) = hv;   // 8B aligned (nglob%4==0)
        } else {
            float* dst = (which == 0) ? g_Q : g_K;
            *(float4*)&dst[((size_t)zz << 20) + (size_t)cch * 1024 + nglob] =
                make_float4(acc[r][0], acc[r][1], acc[r][2], acc[r][3]);
        }
    }
}

// ============================================================
// Kernel 2: k softmax over n (row-wise), x256, f16, packed layout.
// ============================================================
__global__ __launch_bounds__(1024) void k_softmax_kernel() {
    const int z    = blockIdx.y;
    const int lane = threadIdx.x & 31;
    const int w    = threadIdx.x >> 5;
    const int d    = blockIdx.x * 32 + w;
    const float* src = g_K + ((size_t)z << 20) + (size_t)d * 1024;

    float vals[32];
    float m = -3.402823466e38f;
#pragma unroll
    for (int j = 0; j < 32; j++) {
        vals[j] = src[j * 32 + lane];
        m = fmaxf(m, vals[j]);
    }
#pragma unroll
    for (int o = 16; o; o >>= 1) m = fmaxf(m, __shfl_xor_sync(0xffffffffu, m, o));
    float s = 0.f;
#pragma unroll
    for (int j = 0; j < 32; j++) { vals[j] = expf(vals[j] - m); s += vals[j]; }
#pragma unroll
    for (int o = 16; o; o >>= 1) s += __shfl_xor_sync(0xffffffffu, s, o);
    float inv = 256.f / s;

    char* KfB = (char*)g_Kf4;
#pragma unroll
    for (int j = 0; j < 32; j++)
        *(__half*)(KfB + pkoff(z, d, j * 32 + lane)) = __float2half_rn(vals[j] * inv);
}

// ============================================================
// Kernel 3: q denominator: g_qinv[z][n] = 256 / sum_d exp(q[d][n]).
// ============================================================
__global__ __launch_bounds__(256) void q_sum_kernel() {
    __shared__ float red[8][32];
    const int z  = blockIdx.y;
    const int nl = threadIdx.x & 31;
    const int dg = threadIdx.x >> 5;
    const int n  = blockIdx.x * 32 + nl;
    const float* src = g_Q + ((size_t)z << 20) + n;

    float s = 0.f;
#pragma unroll 8
    for (int d = dg * 128; d < dg * 128 + 128; d++) s += expf(src[(size_t)d * 1024]);
    red[dg][nl] = s;
    __syncthreads();
    if (dg == 0) {
        float tot = 0.f;
#pragma unroll
        for (int r = 0; r < 8; r++) tot += red[r][nl];
        g_qinv[z * 1024 + n] = 256.f / tot;
    }
}

// ============================================================
// Kernel 4: q softmax-apply (x256) + transpose -> f16 packed qT[n][d].
// ============================================================
__global__ void q_t_kernel() {
    __shared__ float s[32][33];
    const int z  = blockIdx.z;
    const int d0 = blockIdx.y * 32;
    const int n0 = blockIdx.x * 32;
    const int tx = threadIdx.x, ty = threadIdx.y;
    const float* src = g_Q + ((size_t)z << 20);
    const float inv = g_qinv[z * 1024 + n0 + tx];

#pragma unroll
    for (int i = 0; i < 4; i++) {
        int r = ty + 8 * i;
        s[r][tx] = expf(src[(size_t)(d0 + r) * 1024 + n0 + tx]) * inv;
    }
    __syncthreads();

    char* QfB = (char*)g_Qf4;
#pragma unroll
    for (int i = 0; i < 4; i++) {
        int nl = ty + 8 * i;
        *(__half*)(QfB + pkoff(z, n0 + nl, d0 + tx)) = __float2half_rn(s[tx][nl]);
    }
}

// ============================================================
// Kernel 5: single-pass f16 TN GEMM, bulk-TMA loads + mma.sync.
//   D[m,n'] = sum_k A[m,k]*B[n',k]
// stage 0: A=Vf, B=Kf (256x) -> Cf packed, scale 1/256
// stage 1: A=Cf, B=Qf (256x) -> X [e][n] fp32, scale SCALE/256
// 128x128 tile, K chunk 64 (16 chunks), 3-stage 32KB ring (96KB, 2 CTAs/SM);
// SINGLE-THREAD mbarrier wait + __syncthreads release (no CTA-wide polling);
// loads are 2 x 16KB cp.async.bulk issued by thread 0 per chunk.
// grid (8, 8, 16), block 256.
// ============================================================
#define STAGE_BYTES 32768
#define NSTAGE 3
#define GEMM_SMEM (NSTAGE * STAGE_BYTES + 32)

__global__ __launch_bounds__(256, 2) void gemm_mma_kernel(int stage) {
    extern __shared__ char smem[];
    const uint32_t sbase = smem_u32(smem);
    const uint32_t mbar  = sbase + NSTAGE * STAGE_BYTES;
    const int t    = threadIdx.x;
    const int lane = t & 31;
    const int wid  = t >> 5;

    const char *A, *B;
    if (stage == 0) { A = (const char*)g_Vf4; B = (const char*)g_Kf4; }
    else            { A = (const char*)g_Cf4; B = (const char*)g_Qf4; }
    const int z  = blockIdx.z;
    const int mt = blockIdx.y;
    const int nt = blockIdx.x;
    const char* gA = A + (size_t)(z * 8 + mt) * 32 * 8192;
    const char* gB = B + (size_t)(z * 8 + nt) * 32 * 8192;

    if (t == 0) {
#pragma unroll
        for (int s = 0; s < NSTAGE; s++) mbar_init(mbar + 8 * s, 1);
        asm volatile("fence.proxy.async.shared::cta;" ::: "memory");
    }
    __syncthreads();

    auto issue = [&](int kt) {
        const int st = kt % NSTAGE;
        const uint32_t mb = mbar + 8 * st;
        const uint32_t sb = sbase + st * STAGE_BYTES;
        mbar_expect_tx(mb, STAGE_BYTES);
        bulkcp(sb,         gA + (size_t)kt * 16384, 16384, mb);
        bulkcp(sb + 16384, gB + (size_t)kt * 16384, 16384, mb);
    };
    if (t == 0) { issue(0); issue(1); }

    // compute mapping: warp tile 64x32; wm in {0,1}, wn in {0..3}
    const int wm = wid & 1;
    const int wn = wid >> 1;
    const int aR  = wm * 64 + (lane & 15);
    const int aHi = lane >> 4;
    const int bR  = wn * 32 + (lane & 7) + ((lane >> 4) << 3);
    const int bHi = (lane >> 3) & 1;

    float acc[4][4][4];
#pragma unroll
    for (int i = 0; i < 4; i++)
#pragma unroll
        for (int j = 0; j < 4; j++)
#pragma unroll
            for (int p = 0; p < 4; p++) acc[i][j][p] = 0.f;

#pragma unroll 1
    for (int kt = 0; kt < 16; kt++) {
        // single-waiter: thread 0 waits for this stage's data; bar.sync
        // releases (and memory-orders) the whole CTA.
        if (t == 0) mbar_wait(mbar + 8 * (kt % NSTAGE), (kt / NSTAGE) & 1);
        __syncthreads();                 // also: all warps done reading stage kt-1
        if (t == 0 && kt + 2 < 16) issue(kt + 2);   // overwrites stage (kt-1)%3

        const uint32_t sb = sbase + (kt % NSTAGE) * STAGE_BYTES;
#pragma unroll
        for (int ks = 0; ks < 4; ks++) {
            const uint32_t ab = sb + (ks >> 1) * 8192;          // A block for this k16
            const uint32_t bb = ab + 16384;                      // B block
            const int ch_a = (ks & 1) * 2 + aHi;
            const int ch_b = (ks & 1) * 2 + bHi;
            unsigned bf[2][4];
#pragma unroll
            for (int np = 0; np < 2; np++)
                ldsm4(bf[np], bb + swzoff(bR + np * 16, ch_b));
#pragma unroll
            for (int mb = 0; mb < 4; mb++) {
                unsigned ah[4];
                ldsm4(ah, ab + swzoff(aR + mb * 16, ch_a));
#pragma unroll
                for (int nb = 0; nb < 4; nb++)
                    mma16816(acc[mb][nb], ah, &bf[nb >> 1][(nb & 1) * 2]);
            }
        }
    }

    // ---- epilogue
    const int g  = lane >> 2;
    const int tt = lane & 3;
    const int mw = mt * 128 + wm * 64;
    const int nw = nt * 128 + wn * 32;

    if (stage == 0) {
        char* Cf = (char*)g_Cf4;
        const float sc = 1.f / 256.f;
#pragma unroll
        for (int mb = 0; mb < 4; mb++)
#pragma unroll
            for (int nb = 0; nb < 4; nb++) {
                const float* a = acc[mb][nb];
                int m = mw + mb * 16 + g;
                int k = nw + nb * 8 + 2 * tt;
                *(unsigned*)(Cf + pkoff(z, m,     k)) = packh2(a[0] * sc, a[1] * sc);
                *(unsigned*)(Cf + pkoff(z, m + 8, k)) = packh2(a[2] * sc, a[3] * sc);
            }
    } else {
        const float sc = SCALE / 256.f;
        const size_t zoff = (size_t)z << 20;
#pragma unroll
        for (int mb = 0; mb < 4; mb++)
#pragma unroll
            for (int nb = 0; nb < 4; nb++) {
                const float* a = acc[mb][nb];
                size_t base = zoff + (size_t)(mw + mb * 16 + g) * 1024 + nw + nb * 8 + 2 * tt;
                *(float2*)&g_X[base]            = make_float2(a[0] * sc, a[1] * sc);
                *(float2*)&g_X[base + 8 * 1024] = make_float2(a[2] * sc, a[3] * sc);
            }
    }
}

// ============================================================
// Kernel 6: output projection. Y[b,o,n] = b_out[o] + sum_c X[b,c,n]*w_out[o,c]
// ============================================================
__global__ __launch_bounds__(256) void proj_kernel(const float* __restrict__ wout,
                                                   const float* __restrict__ bout) {
    __shared__ float ws[32][64];
    const int b  = blockIdx.y;
    const int n  = blockIdx.x * 32 + (threadIdx.x & 31);
    const int og = threadIdx.x >> 5;
    const float* X = g_X + ((size_t)b << 22);

    float acc[4];
#pragma unroll
    for (int j = 0; j < 4; j++) acc[j] = bout[og * 4 + j];

    for (int c0 = 0; c0 < 4096; c0 += 64) {
        __syncthreads();
#pragma unroll
        for (int i = 0; i < 2; i++) {
            int idx = threadIdx.x + 256 * i;
            int o = idx >> 4, c4 = (idx & 15) << 2;
            *(float4*)&ws[o][c4] = *(const float4*)&wout[(size_t)o * 4096 + c0 + c4];
        }
        __syncthreads();
#pragma unroll 16
        for (int cl = 0; cl < 64; cl++) {
            float x = X[(size_t)(c0 + cl) * 1024 + n];
#pragma unroll
            for (int j = 0; j < 4; j++) acc[j] += ws[og * 4 + j][cl] * x;
        }
    }
#pragma unroll
    for (int j = 0; j < 4; j++)
        g_Y[((size_t)b * 32 + og * 4 + j) * 1024 + n] = acc[j];
}

// ============================================================
// Kernel 7: per-batch mean/var.
// ============================================================
__global__ __launch_bounds__(1024) void stats_kernel() {
    __shared__ float ss[32], ss2[32];
    const int b = blockIdx.x, t = threadIdx.x;
    const float* Y = g_Y + (size_t)b * 32768;
    float s = 0.f, s2 = 0.f;
#pragma unroll
    for (int k = 0; k < 32; k++) {
        float v = Y[t + 1024 * k];
        s += v; s2 += v * v;
    }
#pragma unroll
    for (int o = 16; o; o >>= 1) {
        s  += __shfl_xor_sync(0xffffffffu, s, o);
        s2 += __shfl_xor_sync(0xffffffffu, s2, o);
    }
    if ((t & 31) == 0) { ss[t >> 5] = s; ss2[t >> 5] = s2; }
    __syncthreads();
    if (t < 32) {
        s = ss[t]; s2 = ss2[t];
#pragma unroll
        for (int o = 16; o; o >>= 1) {
            s  += __shfl_xor_sync(0xffffffffu, s, o);
            s2 += __shfl_xor_sync(0xffffffffu, s2, o);
        }
        if (t == 0) {
            float mean = s * (1.f / 32768.f);
            g_stats[b]     = mean;
            g_stats[4 + b] = s2 * (1.f / 32768.f) - mean * mean;
        }
    }
}

// ============================================================
// Kernel 8: GroupNorm finalize -> d_out.
// ============================================================
__global__ void gn_kernel(const float* __restrict__ gamma,
                          const float* __restrict__ beta,
                          float* __restrict__ out) {
    int idx = blockIdx.x * 256 + threadIdx.x;
    int b = idx >> 15;
    int o = (idx >> 10) & 31;
    float mean = g_stats[b];
    float rstd = rsqrtf(g_stats[4 + b] + EPSGN);
    out[idx] = (g_Y[idx] - mean) * rstd * gamma[o] + beta[o];
}

// ============================================================
extern "C" void kernel_launch(void* const* d_in, const int* in_sizes, int n_in,
                              void* d_out, int out_size) {
    (void)in_sizes; (void)n_in; (void)out_size;
    const float* image = (const float*)d_in[0];
    const float* w_qkv = (const float*)d_in[1];
    const float* b_qkv = (const float*)d_in[2];
    const float* w_out = (const float*)d_in[3];
    const float* b_out = (const float*)d_in[4];
    const float* gamma = (const float*)d_in[5];
    const float* beta  = (const float*)d_in[6];
    float* out = (float*)d_out;

    cudaFuncSetAttribute(gemm_mma_kernel,
                         cudaFuncAttributeMaxDynamicSharedMemorySize, GEMM_SMEM);

    qkv_kernel<<<dim3(8, 192, 4), 256>>>(image, w_qkv, b_qkv);
    k_softmax_kernel<<<dim3(32, 16), 1024>>>();
    q_sum_kernel<<<dim3(32, 16), 256>>>();
    q_t_kernel<<<dim3(32, 32, 16), dim3(32, 8)>>>();
    gemm_mma_kernel<<<dim3(8, 8, 16), 256, GEMM_SMEM>>>(0);  // Cf = V * K^T
    gemm_mma_kernel<<<dim3(8, 8, 16), 256, GEMM_SMEM>>>(1);  // X  = Cf * QT^T
    proj_kernel<<<dim3(32, 4), 256>>>(w_out, b_out);
    stats_kernel<<<4, 1024>>>();
    gn_kernel<<<512, 256>>>(gamma, beta, out);
}